// round 3
// baseline (speedup 1.0000x reference)
#include <cuda_runtime.h>
#include <math.h>

#define BE 64
#define NOCT 32
#define NSAMP 32768
#define TPB 256
#define NBLK 256            // 2 blocks/SM x 148 SMs = 296 slots >= 256 (barrier-safe)
#define WPB 8               // warps per block
#define CHUNKS 32           // warps (chunks of 1024 samples) per be
#define SPT 32              // samples per thread (all same be)

// Scratch (no allocation allowed). g_wmax slots written exactly once per
// launch -> no init needed, deterministic across graph replays.
__device__ float    g_wmax[BE * CHUNKS];
__device__ int      g_count;
__device__ volatile int g_phase;

// Sense-reversing grid barrier; state self-restores across replays.
__device__ __forceinline__ void grid_barrier() {
    __syncthreads();
    if (threadIdx.x == 0) {
        int ph = g_phase;
        __threadfence();
        if (atomicAdd(&g_count, 1) == NBLK - 1) {
            g_count = 0;
            __threadfence();
            g_phase = ph ^ 1;
        } else {
            while (g_phase == ph) { __nanosleep(32); }
        }
        __threadfence();
    }
    __syncthreads();
}

__global__ void __launch_bounds__(TPB, 2)
fused_kernel(const float* __restrict__ f0_in,
             const float* __restrict__ dec_in,
             const float* __restrict__ sp_in,
             float* __restrict__ out) {
    __shared__ float sf[BE * NOCT];
    __shared__ float sa[BE * NOCT];
    __shared__ int   snact[BE];

    const int tid  = threadIdx.x;
    const int lane = tid & 31;

    // ---- Phase 0: every block redundantly builds the 64-be param table ----
    // (phase-critical path: separate RN ops + sequential f32 cumsum, matching
    //  the reference's f32 rounding exactly)
    if (tid < BE) {
        const float MINF   = (float)(20.0 / 11025.0);
        const float FRANGE = (float)(3000.0 / 11025.0 - 20.0 / 11025.0);
        const float PI_F   = (float)3.14159265358979323846;
        const float RESF   = (float)((1.0 - 0.01) * 0.99);

        float f0  = fabsf(f0_in[tid]);
        float fsc = __fmul_rn(__fadd_rn(MINF, __fmul_rn(f0, FRANGE)), PI_F);
        float sp  = sp_in[tid];

        float x  = dec_in[tid];
        float s1 = 1.0f / (1.0f + expf(-x));
        float s2 = 1.0f / (1.0f + expf(-s1));
        float d  = __fadd_rn(0.01f, __fmul_rn(s2, RESF));
        float ld = logf(__fadd_rn(d, 1e-12f));

        float fac = 0.0f, cl = 0.0f;
        int nact = 0;
        for (int o = 0; o < NOCT; o++) {
            fac = __fadd_rn(fac, sp);
            cl  = __fadd_rn(cl, ld);
            float f0s = __fmul_rn(fsc, fac);
            sf[tid * NOCT + o] = f0s;
            sa[tid * NOCT + o] = expf(cl);
            if (f0s < 1.0f) nact = o + 1;   // monotone -> prefix mask
        }
        snact[tid] = nact;
    }
    __syncthreads();

    // ---- Phase 1: one warp = one (be, 1024-sample chunk). Octave loop
    //      outer; 32 independent per-thread sample chains inner (full ILP).
    const int W     = blockIdx.x * WPB + (tid >> 5);
    const int be    = W & (BE - 1);          // warp-uniform
    const int chunk = W >> 6;                // 0..31
    const int nact  = snact[be];

    // thread owns samples: chunk*1024 + g*128 + lane*4 + j  (g=0..7, j=0..3)
    const float tb = (float)(chunk * 1024 + lane * 4 + 1);

    const float INV2PI = 0.15915494309189535f;
    const float MAGIC  = 12582912.0f;        // 1.5 * 2^23
    const float HI     = 6.2831855f;         // fl32(2*pi)
    const float LO     = (float)(6.283185307179586476925286766559
                                 - (double)6.2831855f);

    float acc[SPT];
    #pragma unroll
    for (int k = 0; k < SPT; k++) acc[k] = 0.0f;

    const float* fp = sf + be * NOCT;
    const float* ap = sa + be * NOCT;

    for (int o = 0; o < nact; o++) {
        const float f = fp[o];               // uniform LDS broadcast
        const float a = ap[o];
        #pragma unroll
        for (int k = 0; k < SPT; k++) {
            float t  = tb + (float)((k >> 2) * 128 + (k & 3)); // exact int
            float p  = __fmul_rn(f, t);      // reference fl32 phase
            float bq = __fmaf_rn(p, INV2PI, MAGIC);
            float kk = __fadd_rn(bq, -MAGIC);            // = round(p/2pi)
            float r  = __fmaf_rn(kk, -HI, p);
            r        = __fmaf_rn(kk, -LO, r);            // exact CW reduce
            acc[k]   = __fmaf_rn(__sinf(r), a, acc[k]);
        }
    }

    // per-warp max-abs over its 1024 samples
    float m = 0.0f;
    #pragma unroll
    for (int k = 0; k < SPT; k++) m = fmaxf(m, fabsf(acc[k]));
    #pragma unroll
    for (int off = 16; off > 0; off >>= 1)
        m = fmaxf(m, __shfl_xor_sync(0xFFFFFFFFu, m, off));
    if (lane == 0) g_wmax[be * CHUNKS + chunk] = m;

    grid_barrier();

    // ---- Phase 2: each warp redundantly reduces its be's 32 chunk-maxes ----
    float v = g_wmax[be * CHUNKS + lane];
    #pragma unroll
    for (int off = 16; off > 0; off >>= 1)
        v = fmaxf(v, __shfl_xor_sync(0xFFFFFFFFu, v, off));
    float inv = 1.0f / (v + 1e-8f);
    inv = __shfl_sync(0xFFFFFFFFu, inv, 0);

    // ---- Phase 3: normalize from registers, vectorized stores ----
    float4* o4 = (float4*)(out + be * NSAMP + chunk * 1024);
    #pragma unroll
    for (int g = 0; g < 8; g++) {
        float4 w;
        w.x = acc[g * 4 + 0] * inv;
        w.y = acc[g * 4 + 1] * inv;
        w.z = acc[g * 4 + 2] * inv;
        w.w = acc[g * 4 + 3] * inv;
        o4[g * 32 + lane] = w;
    }
}

extern "C" void kernel_launch(void* const* d_in, const int* in_sizes, int n_in,
                              void* d_out, int out_size) {
    const float* f0  = (const float*)d_in[0];
    const float* dec = (const float*)d_in[1];
    const float* sp  = (const float*)d_in[2];
    float* out = (float*)d_out;

    fused_kernel<<<NBLK, TPB>>>(f0, dec, sp, out);
}

// round 4
// speedup vs baseline: 1.4562x; 1.4562x over previous
#include <cuda_runtime.h>
#include <math.h>

#define BE 64
#define NOCT 32
#define NSAMP 32768
#define TPB 256
#define CHUNK_SAMP 2048          // samples per block in kernel A
#define NCHUNK (NSAMP / CHUNK_SAMP)   // 16
#define SPT 8                    // samples per thread (2 groups x 4)

// Per-(be,chunk) max scratch: every slot written exactly once per launch by
// kernel A before kernel B reads it -> no init needed, replay-deterministic.
__device__ float g_wmax[BE * NCHUNK];

// ---------------------------------------------------------------------------
// Kernel A: oscillator bank. Block = (chunk of 2048 samples, be).
// Octave loop outer, 8 independent per-thread sample chains inner (ILP).
// Phase-critical math replicates the reference's f32 rounding exactly.
// ---------------------------------------------------------------------------
__global__ void __launch_bounds__(TPB)
osc_kernel(const float* __restrict__ f0_in,
           const float* __restrict__ dec_in,
           const float* __restrict__ sp_in,
           float* __restrict__ out) {
    __shared__ float sf[NOCT];
    __shared__ float sa[NOCT];
    __shared__ int   snact;

    const int be    = blockIdx.y;
    const int chunk = blockIdx.x;
    const int tid   = threadIdx.x;

    // ---- per-block param setup for this be (1 thread, ~500 cyc, hidden) ----
    if (tid == 0) {
        const float MINF   = (float)(20.0 / 11025.0);
        const float FRANGE = (float)(3000.0 / 11025.0 - 20.0 / 11025.0);
        const float PI_F   = (float)3.14159265358979323846;
        const float RESF   = (float)((1.0 - 0.01) * 0.99);

        float f0  = fabsf(f0_in[be]);
        float fsc = __fmul_rn(__fadd_rn(MINF, __fmul_rn(f0, FRANGE)), PI_F);
        float sp  = sp_in[be];

        float x  = dec_in[be];
        float s1 = 1.0f / (1.0f + expf(-x));
        float s2 = 1.0f / (1.0f + expf(-s1));
        float d  = __fadd_rn(0.01f, __fmul_rn(s2, RESF));
        float ld = logf(__fadd_rn(d, 1e-12f));

        float fac = 0.0f, cl = 0.0f;
        int nact = 0;
        #pragma unroll 1
        for (int o = 0; o < NOCT; o++) {
            fac = __fadd_rn(fac, sp);        // sequential f32 cumsum
            cl  = __fadd_rn(cl, ld);
            float f0s = __fmul_rn(fsc, fac);
            sf[o] = f0s;
            sa[o] = expf(cl);
            if (f0s < 1.0f) nact = o + 1;    // monotone -> prefix mask
        }
        snact = nact;
    }
    __syncthreads();
    const int nact = snact;

    // thread owns samples: chunk*2048 + g*1024 + tid*4 + j  (g=0..1, j=0..3)
    const float tb = (float)(chunk * CHUNK_SAMP + tid * 4 + 1);
    float tv[SPT];
    #pragma unroll
    for (int k = 0; k < SPT; k++)
        tv[k] = tb + (float)((k >> 2) * 1024 + (k & 3));   // exact integers

    const float INV2PI = 0.15915494309189535f;
    const float MAGIC  = 12582912.0f;        // 1.5 * 2^23
    const float HI     = 6.2831855f;         // fl32(2*pi)
    const float LO     = (float)(6.283185307179586476925286766559
                                 - (double)6.2831855f);

    float acc[SPT];
    #pragma unroll
    for (int k = 0; k < SPT; k++) acc[k] = 0.0f;

    #pragma unroll 1
    for (int o = 0; o < nact; o++) {
        const float f = sf[o];               // broadcast LDS
        const float a = sa[o];
        #pragma unroll
        for (int k = 0; k < SPT; k++) {
            float p  = __fmul_rn(f, tv[k]);  // reference fl32 phase
            float bq = __fmaf_rn(p, INV2PI, MAGIC);
            float kk = __fadd_rn(bq, -MAGIC);        // round(p / 2pi)
            float r  = __fmaf_rn(kk, -HI, p);
            r        = __fmaf_rn(kk, -LO, r);        // exact CW reduction
            acc[k]   = __fmaf_rn(__sinf(r), a, acc[k]);
        }
    }

    // unnormalized output, float4 stores
    float4* o4 = (float4*)(out + be * NSAMP + chunk * CHUNK_SAMP);
    #pragma unroll
    for (int g = 0; g < 2; g++) {
        float4 w;
        w.x = acc[g * 4 + 0];
        w.y = acc[g * 4 + 1];
        w.z = acc[g * 4 + 2];
        w.w = acc[g * 4 + 3];
        o4[g * TPB + tid] = w;
    }

    // block max-abs -> one slot (no atomics, no init)
    float m = 0.0f;
    #pragma unroll
    for (int k = 0; k < SPT; k++) m = fmaxf(m, fabsf(acc[k]));
    #pragma unroll
    for (int off = 16; off > 0; off >>= 1)
        m = fmaxf(m, __shfl_xor_sync(0xFFFFFFFFu, m, off));

    __shared__ float wm[TPB / 32];
    if ((tid & 31) == 0) wm[tid >> 5] = m;
    __syncthreads();
    if (tid < TPB / 32) {
        float mm = wm[tid];
        #pragma unroll
        for (int off = TPB / 64; off > 0; off >>= 1)
            mm = fmaxf(mm, __shfl_xor_sync(0xFFu, mm, off));
        if (tid == 0) g_wmax[be * NCHUNK + chunk] = mm;
    }
}

// ---------------------------------------------------------------------------
// Kernel B: reduce 16 chunk-maxes per be, normalize in place (float4).
// Block = (segment of 4096 samples, be).
// ---------------------------------------------------------------------------
__global__ void __launch_bounds__(TPB)
norm_kernel(float4* __restrict__ out4) {
    const int be  = blockIdx.y;
    const int seg = blockIdx.x;          // 0..7, each 1024 float4
    const int tid = threadIdx.x;
    const int lane = tid & 31;

    float v = g_wmax[be * NCHUNK + (lane & (NCHUNK - 1))];
    #pragma unroll
    for (int off = 8; off > 0; off >>= 1)
        v = fmaxf(v, __shfl_xor_sync(0xFFFFFFFFu, v, off));
    const float inv = 1.0f / (v + 1e-8f);

    float4* p = out4 + be * (NSAMP / 4) + seg * 1024;
    #pragma unroll
    for (int g = 0; g < 4; g++) {
        float4 w = p[g * TPB + tid];
        w.x *= inv; w.y *= inv; w.z *= inv; w.w *= inv;
        p[g * TPB + tid] = w;
    }
}

extern "C" void kernel_launch(void* const* d_in, const int* in_sizes, int n_in,
                              void* d_out, int out_size) {
    const float* f0  = (const float*)d_in[0];
    const float* dec = (const float*)d_in[1];
    const float* sp  = (const float*)d_in[2];
    float* out = (float*)d_out;

    dim3 gA(NCHUNK, BE);                 // 16 x 64 = 1024 blocks
    osc_kernel<<<gA, TPB>>>(f0, dec, sp, out);
    dim3 gB(8, BE);                      // 8 x 64 = 512 blocks
    norm_kernel<<<gB, TPB>>>((float4*)out);
}